// round 10
// baseline (speedup 1.0000x reference)
#include <cuda_runtime.h>

#define BB 2
#define NQv 1024
#define NKv 1024
#define DD 512
#define HH 32

// Scratch (no cudaMalloc allowed). Raw f32 projections.
__device__ __align__(16) float g_hk[BB * NKv * HH];   // keys@W1[:D] + b1
__device__ __align__(16) float g_hq[BB * NQv * HH];   // queries@W1[D:]

__device__ __forceinline__ float tanh_fast(float x) {
    float y; asm("tanh.approx.f32 %0, %1;" : "=f"(y) : "f"(x)); return y;
}

// ---------------------------------------------------------------------------
// Projection v10 (register-prefetch double buffer):
// C[2048,32] = A[2048,512] @ W[512,32] per tensor. Grid (64,2) = 128 blocks,
// 256 thr, 32 rows/block, 4 chunks of 128 d. While chunk c is computed from
// smem, chunk c+1's LDGs are in flight into registers; the compute phase
// (~1024 fma-cyc) covers the ~600-cyc memory latency that previously
// serialized 4x per block. Smem single-buffered (32 KB).
// ---------------------------------------------------------------------------
__global__ __launch_bounds__(256) void proj_kernel(
    const float* __restrict__ keys, const float* __restrict__ queries,
    const float* __restrict__ W1, const float* __restrict__ b1)
{
    __shared__ float as[32][128];   // A chunk (16 KB)
    __shared__ float ws[128][32];   // W chunk (16 KB)

    const int z    = blockIdx.y;
    const int tid  = threadIdx.x;
    const int h    = tid & 31;
    const int warp = tid >> 5;
    const int row0 = blockIdx.x * 32;
    const float* __restrict__ src = z ? queries : keys;

    float4* const av = (float4*)&as[0][0];
    float4* const wv = (float4*)&ws[0][0];

    float4 ra[4], rw[4];
    // Prologue: prefetch chunk 0.
    {
        const float4* __restrict__ ag = (const float4*)(src + (size_t)row0 * DD);
        const float4* __restrict__ wg = (const float4*)(W1 + (size_t)(z * DD) * HH);
        #pragma unroll
        for (int i = 0; i < 4; ++i) {
            const int idx = tid + i * 256;
            ra[i] = __ldg(&ag[(size_t)(idx >> 5) * (DD / 4) + (idx & 31)]);
            rw[i] = __ldg(&wg[idx]);
        }
    }

    float acc0 = 0.f, acc1 = 0.f, acc2 = 0.f, acc3 = 0.f;

    #pragma unroll
    for (int c = 0; c < 4; ++c) {
        // Stage prefetched chunk c into smem.
        #pragma unroll
        for (int i = 0; i < 4; ++i) {
            const int idx = tid + i * 256;
            av[idx] = ra[i];
            wv[idx] = rw[i];
        }
        __syncthreads();

        // Kick off chunk c+1 loads; they complete during the compute below.
        if (c < 3) {
            const float4* __restrict__ ag =
                (const float4*)(src + (size_t)row0 * DD + (c + 1) * 128);
            const float4* __restrict__ wg =
                (const float4*)(W1 + (size_t)(z * DD + (c + 1) * 128) * HH);
            #pragma unroll
            for (int i = 0; i < 4; ++i) {
                const int idx = tid + i * 256;
                ra[i] = __ldg(&ag[(size_t)(idx >> 5) * (DD / 4) + (idx & 31)]);
                rw[i] = __ldg(&wg[idx]);
            }
        }

        #pragma unroll 8
        for (int d4 = 0; d4 < 32; ++d4) {
            const float4 a0 = *(const float4*)&as[4 * warp + 0][d4 * 4];
            const float4 a1 = *(const float4*)&as[4 * warp + 1][d4 * 4];
            const float4 a2 = *(const float4*)&as[4 * warp + 2][d4 * 4];
            const float4 a3 = *(const float4*)&as[4 * warp + 3][d4 * 4];
            const float w0  = ws[d4 * 4 + 0][h];
            const float w1v = ws[d4 * 4 + 1][h];
            const float w2v = ws[d4 * 4 + 2][h];
            const float w3v = ws[d4 * 4 + 3][h];
            acc0 = fmaf(a0.x, w0, acc0); acc0 = fmaf(a0.y, w1v, acc0);
            acc0 = fmaf(a0.z, w2v, acc0); acc0 = fmaf(a0.w, w3v, acc0);
            acc1 = fmaf(a1.x, w0, acc1); acc1 = fmaf(a1.y, w1v, acc1);
            acc1 = fmaf(a1.z, w2v, acc1); acc1 = fmaf(a1.w, w3v, acc1);
            acc2 = fmaf(a2.x, w0, acc2); acc2 = fmaf(a2.y, w1v, acc2);
            acc2 = fmaf(a2.z, w2v, acc2); acc2 = fmaf(a2.w, w3v, acc2);
            acc3 = fmaf(a3.x, w0, acc3); acc3 = fmaf(a3.y, w1v, acc3);
            acc3 = fmaf(a3.z, w2v, acc3); acc3 = fmaf(a3.w, w3v, acc3);
        }
        __syncthreads();
    }

    const float bias = (z == 0) ? __ldg(&b1[h]) : 0.f;
    float* __restrict__ dst = (z == 0) ? g_hk : g_hq;
    const int r0 = row0 + 4 * warp;
    dst[(size_t)(r0 + 0) * HH + h] = acc0 + bias;
    dst[(size_t)(r0 + 1) * HH + h] = acc1 + bias;
    dst[(size_t)(r0 + 2) * HH + h] = acc2 + bias;
    dst[(size_t)(r0 + 3) * HH + h] = acc3 + bias;
}

// ---------------------------------------------------------------------------
// Scoring v10: proven R2 inner math, quarter-size blocks for tail smoothing.
// 32q x 32k tile, 128 thr (16 k-thr x 8 q-thr), thread = 4q x 2k.
// Grid 2048 -> per-SM completion skew ~t_b/4 of the 64q version.
// ---------------------------------------------------------------------------
__global__ __launch_bounds__(128) void score_kernel(
    const float* __restrict__ W2, const float* __restrict__ b2,
    float* __restrict__ out)
{
    __shared__ float hqs[32][32];
    __shared__ float hks[32][33];
    __shared__ float w2s[32];

    const int b   = blockIdx.z;
    const int q0  = blockIdx.y * 32;
    const int k0  = blockIdx.x * 32;
    const int tid = threadIdx.x;

    {
        // hq tile: 32*32 floats = 256 float4, 2/thread
        const float4* __restrict__ hq_g =
            (const float4*)(g_hq + (size_t)(b * NQv + q0) * HH);
        float4* hqv = (float4*)&hqs[0][0];
        hqv[tid]       = __ldg(&hq_g[tid]);
        hqv[tid + 128] = __ldg(&hq_g[tid + 128]);
        // hk tile: 32*32 floats scalar into padded array, 8/thread
        const float* __restrict__ hk_g = g_hk + (size_t)(b * NKv + k0) * HH;
        #pragma unroll
        for (int it = 0; it < 8; ++it) {
            const int i = tid + it * 128;
            hks[i >> 5][i & 31] = __ldg(&hk_g[i]);
        }
        if (tid < 32) w2s[tid] = __ldg(&W2[tid]);
    }
    __syncthreads();

    const int kk = (tid & 15) * 2;
    const int qq = (tid >> 4) * 4;

    float a00 = 0.f, a01 = 0.f, a10 = 0.f, a11 = 0.f;
    float a20 = 0.f, a21 = 0.f, a30 = 0.f, a31 = 0.f;

    #pragma unroll
    for (int h = 0; h < HH; ++h) {
        const float w   = w2s[h];
        const float bk0 = hks[kk][h];
        const float bk1 = hks[kk + 1][h];
        const float q0v = hqs[qq + 0][h];
        const float q1v = hqs[qq + 1][h];
        const float q2v = hqs[qq + 2][h];
        const float q3v = hqs[qq + 3][h];
        a00 = fmaf(w, tanh_fast(q0v + bk0), a00);
        a01 = fmaf(w, tanh_fast(q0v + bk1), a01);
        a10 = fmaf(w, tanh_fast(q1v + bk0), a10);
        a11 = fmaf(w, tanh_fast(q1v + bk1), a11);
        a20 = fmaf(w, tanh_fast(q2v + bk0), a20);
        a21 = fmaf(w, tanh_fast(q2v + bk1), a21);
        a30 = fmaf(w, tanh_fast(q3v + bk0), a30);
        a31 = fmaf(w, tanh_fast(q3v + bk1), a31);
    }

    const float bias = __ldg(b2);
    float* __restrict__ o =
        out + (size_t)(b * NQv + q0 + qq) * NKv + k0 + kk;
    *(float2*)(o + 0 * NKv) = make_float2(a00 + bias, a01 + bias);
    *(float2*)(o + 1 * NKv) = make_float2(a10 + bias, a11 + bias);
    *(float2*)(o + 2 * NKv) = make_float2(a20 + bias, a21 + bias);
    *(float2*)(o + 3 * NKv) = make_float2(a30 + bias, a31 + bias);
}

extern "C" void kernel_launch(void* const* d_in, const int* in_sizes, int n_in,
                              void* d_out, int out_size)
{
    const float* keys    = (const float*)d_in[0];
    const float* queries = (const float*)d_in[1];
    const float* W1      = (const float*)d_in[2];
    const float* b1      = (const float*)d_in[3];
    const float* W2      = (const float*)d_in[4];
    const float* b2      = (const float*)d_in[5];
    float* out = (float*)d_out;

    proj_kernel<<<dim3(64, 2, 1), 256>>>(keys, queries, W1, b1);
    score_kernel<<<dim3(NKv / 32, NQv / 32, BB), 128>>>(W2, b2, out);
}